// round 8
// baseline (speedup 1.0000x reference)
#include <cuda_runtime.h>

#define HH 64
#define MM 256
#define VV 64
#define RFQ 16
#define NCHUNK 128
#define NB 4          // batches per block
#define NT 256        // threads per block
#define NGRID 128
#define TS 68         // padded row stride (floats): conflict-free for float4 row reads + column reads

// ---- precomputed tables in device globals (filled by setup kernel) ----
__device__ float VPg[12288];   // [3][64 vocab][64 j]
__device__ float RVTg[12288];  // [64 i][192 row]
__device__ float ATg[4096];    // [64 c][64 i]
__device__ float A0g[64];
__device__ float RV0g[192];

// smem offsets (floats)
#define OFF_RVT   0            // 12288
#define OFF_AT    12288        // 4096
#define OFF_A0    16384        // 64
#define OFF_RV0   16448        // 192
#define OFF_WALL  16640        // 192*68 = 13056 (all W_hh rows, padded)
#define OFF_TILE  29696        // 4 * 64*68 = 17408
#define OFF_HS    47104        // 4 * 2 * 64
#define OFF_QS    47616        // 4 * 64
#define OFF_SS    47872
#define OFF_ES    48128
#define OFF_RS    48384
#define OFF_TOK   48640        // 64 ints
#define SMEM_FLOATS 48704      // 194816 bytes

typedef unsigned long long ull;

__device__ __forceinline__ void gbar(int id) {
    asm volatile("bar.sync %0, 64;" :: "r"(id) : "memory");
}
__device__ __forceinline__ float sigmoidf_(float x) {
    float e = __expf(-x);
    return __fdividef(1.f, 1.f + e);
}
__device__ __forceinline__ float tanhf_(float x) {
    float e = __expf(2.f * x);
    return 1.f - __fdividef(2.f, e + 1.f);
}
__device__ __forceinline__ ull pk(float a, float b) {
    ull r; asm("mov.b64 %0, {%1,%2};" : "=l"(r) : "f"(a), "f"(b)); return r;
}
__device__ __forceinline__ void fma2(ull& d, ull a, ull b) {
    asm("fma.rn.f32x2 %0, %1, %2, %0;" : "+l"(d) : "l"(a), "l"(b));
}
__device__ __forceinline__ float2 upk(ull a) {
    float2 f; asm("mov.b64 {%0,%1}, %2;" : "=f"(f.x), "=f"(f.y) : "l"(a)); return f;
}

// ---- setup kernel: fold all token/attention algebra once ----
__global__ void setup_k(const float* __restrict__ embed_w, const float* __restrict__ w_ih,
                        const float* __restrict__ b_ih, const float* __restrict__ key_w,
                        const float* __restrict__ val_w, const float* __restrict__ val_b,
                        const float* __restrict__ query_w, const float* __restrict__ query_b)
{
    const int idx = blockIdx.x * 256 + threadIdx.x;
    if (idx < 12288) {
        // VP[g][v][jj] = emb[v] . W_ih_x[row] + b_ih[row],  row = g*64+jj
        const int g = idx >> 12, v = (idx >> 6) & 63, jj = idx & 63;
        const int row = g * 64 + jj;
        float acc = b_ih[row];
#pragma unroll 8
        for (int c = 0; c < 64; c++) acc = fmaf(embed_w[v * 64 + c], w_ih[row * 128 + c], acc);
        VPg[idx] = acc;
    } else if (idx < 24576) {
        // RVT[i][row] = sum_k W_ih_ret[row][k] * val_w[k][i]
        const int t = idx - 12288;
        const int i = t / 192, row = t % 192;
        float acc = 0.f;
#pragma unroll 8
        for (int k = 0; k < 64; k++) acc = fmaf(w_ih[row * 128 + 64 + k], val_w[k * 64 + i], acc);
        RVTg[i * 192 + row] = acc;
    } else if (idx < 28672) {
        // AT[c][i] = scale * sum_k key_w[k][i]*query_w[k][c]
        const int t = idx - 24576;
        const int c = t >> 6, i = t & 63;
        float acc = 0.f;
#pragma unroll 8
        for (int k = 0; k < 64; k++) acc = fmaf(key_w[k * 64 + i], query_w[k * 64 + c], acc);
        ATg[c * 64 + i] = acc * 0.125f;
    } else if (idx < 28736) {
        const int i = idx - 28672;
        float acc = 0.f;
#pragma unroll 8
        for (int k = 0; k < 64; k++) acc = fmaf(key_w[k * 64 + i], query_b[k], acc);
        A0g[i] = acc * 0.125f;
    } else if (idx < 28928) {
        const int row = idx - 28736;
        float acc = 0.f;
#pragma unroll 8
        for (int k = 0; k < 64; k++) acc = fmaf(w_ih[row * 128 + 64 + k], val_b[k], acc);
        RV0g[row] = acc;
    }
}

__global__ void __launch_bounds__(NT, 1) ffm_kernel(
    const int*   __restrict__ seq,
    const float* __restrict__ memory,
    const float* __restrict__ w_hh,
    const float* __restrict__ b_hh,
    const float* __restrict__ head_w,
    const float* __restrict__ head_b,
    float* __restrict__ out)
{
    extern __shared__ float sm[];
    float* RVT = sm + OFF_RVT;
    float* AT  = sm + OFF_AT;
    float* A0  = sm + OFF_A0;
    float* RV0 = sm + OFF_RV0;

    const int tid = threadIdx.x;
    const int j   = tid & 63;
    const int bl  = tid >> 6;
    const int bg  = blockIdx.x * NB + bl;

    // ---- copy tables + weights into shared ----
    for (int e = tid; e < 12288; e += NT) {
        RVT[e] = RVTg[e];
        const int row = e >> 6, i = e & 63;
        sm[OFF_WALL + row * TS + i] = w_hh[e];
    }
    for (int e = tid; e < 4096; e += NT) AT[e] = ATg[e];
    if (tid < 64)  A0[tid]  = A0g[tid];
    if (tid < 192) RV0[tid] = RV0g[tid];

    float* TILEb = sm + OFF_TILE + bl * (64 * TS);
    float* HSb   = sm + OFF_HS   + bl * 128;
    float* QSb   = sm + OFF_QS   + bl * 64;
    float* SSb   = sm + OFF_SS   + bl * 64;
    float* ESb   = sm + OFF_ES   + bl * 64;
    float* RSb   = sm + OFF_RS   + bl * 64;
    int*   TOKb  = (int*)(sm + OFF_TOK) + bl * 16;

    HSb[j] = 0.f; HSb[64 + j] = 0.f;
    float h = 0.f;
    const float* memb = memory + (size_t)bg * (MM * HH);
    const int*   seqb = seq + (size_t)bg * 2048;
    const int barid = bl + 1;
    const ull BHR2 = pk(b_hh[j], 0.f);
    const ull BHZ2 = pk(b_hh[64 + j], 0.f);
    const ull BHN2 = pk(b_hh[128 + j], 0.f);
    __syncthreads();

#pragma unroll 1
    for (int ch = 0; ch < NCHUNK; ch++) {
        // tokens + query (h lives in HS buffer 0 at chunk boundaries)
        if (j < 16) TOKb[j] = seqb[ch * RFQ + j];
        float qt = A0[j];
#pragma unroll 8
        for (int c = 0; c < 64; c++) qt = fmaf(AT[c * 64 + j], HSb[c], qt);
        QSb[j] = qt;

        // register-prefetch tile 0 (global loads: no smem hazard)
        float4 pf[16];
        const float4* mt4 = (const float4*)memb;
#pragma unroll
        for (int it = 0; it < 16; it++) pf[it] = mt4[it * 64 + j];
        gbar(barid);

        // ---- single pass over memory: online softmax + weighted accumulation ----
        float Mx = -1e30f, D = 0.f, macc = 0.f;
#pragma unroll 1
        for (int t4 = 0; t4 < 4; t4++) {
            // store prefetched tile
#pragma unroll
            for (int it = 0; it < 16; it++) {
                const int e4 = it * 64 + j;
                const int r = e4 >> 4, c4 = e4 & 15;
                *(float4*)(TILEb + r * TS + c4 * 4) = pf[it];
            }
            // prefetch next tile while this one is consumed
            if (t4 < 3) {
                const float4* nt4 = mt4 + (t4 + 1) * 1024;
#pragma unroll
                for (int it = 0; it < 16; it++) pf[it] = nt4[it * 64 + j];
            }
            gbar(barid);
            // score for row m=j
            float s = 0.f;
            {
                const float4* q4 = (const float4*)QSb;
                const float4* row4 = (const float4*)(TILEb + j * TS);
#pragma unroll
                for (int i4 = 0; i4 < 16; i4++) {
                    const float4 qv = q4[i4], rv = row4[i4];
                    s = fmaf(qv.x, rv.x, s); s = fmaf(qv.y, rv.y, s);
                    s = fmaf(qv.z, rv.z, s); s = fmaf(qv.w, rv.w, s);
                }
            }
            SSb[j] = s;
            gbar(barid);
            float tm = -1e30f;
#pragma unroll 8
            for (int m = 0; m < 64; m++) tm = fmaxf(tm, SSb[m]);
            const float nM = fmaxf(Mx, tm);
            const float alpha = __expf(Mx - nM);
            ESb[j] = __expf(s - nM);
            gbar(barid);
            macc *= alpha; D *= alpha;
#pragma unroll 8
            for (int m = 0; m < 64; m++) {
                const float em = ESb[m];
                macc = fmaf(em, TILEb[m * TS + j], macc);
                D += em;
            }
            Mx = nM;
            gbar(barid);
        }
        RSb[j] = macc / D;
        gbar(barid);

        // r_proj rows {j, 64+j, 128+j}
        float rp_r = RV0[j], rp_z = RV0[64 + j], rp_n = RV0[128 + j];
#pragma unroll 8
        for (int i = 0; i < 64; i++) {
            const float rv = RSb[i];
            rp_r = fmaf(RVT[i * 192 + j], rv, rp_r);
            rp_z = fmaf(RVT[i * 192 + 64 + j], rv, rp_z);
            rp_n = fmaf(RVT[i * 192 + 128 + j], rv, rp_n);
        }

        // ---- reload all W_hh weights into registers (packed f32x2), once per chunk ----
        ull wr2[32], wz2[32], wn2[32];
        {
            const float4* wrp = (const float4*)(sm + OFF_WALL + j * TS);
            const float4* wzp = (const float4*)(sm + OFF_WALL + (64 + j) * TS);
            const float4* wnp = (const float4*)(sm + OFF_WALL + (128 + j) * TS);
#pragma unroll
            for (int i4 = 0; i4 < 16; i4++) {
                float4 a = wrp[i4]; wr2[2 * i4] = pk(a.x, a.y); wr2[2 * i4 + 1] = pk(a.z, a.w);
                float4 b = wzp[i4]; wz2[2 * i4] = pk(b.x, b.y); wz2[2 * i4 + 1] = pk(b.z, b.w);
                float4 c = wnp[i4]; wn2[2 * i4] = pk(c.x, c.y); wn2[2 * i4 + 1] = pk(c.z, c.w);
            }
        }

        // ---- 16 GRU steps (FFMA2 dot products) ----
        int curl = 0;
#pragma unroll 1
        for (int st = 0; st < RFQ; st++) {
            const int tok = TOKb[st];
            const float gxr = VPg[tok * 64 + j] + rp_r;
            const float gxz = VPg[4096 + tok * 64 + j] + rp_z;
            const float gxn = VPg[8192 + tok * 64 + j] + rp_n;
            const float4* h4 = (const float4*)(HSb + curl * 64);
            ull ar = BHR2, az = BHZ2, an = BHN2;
#pragma unroll
            for (int i4 = 0; i4 < 16; i4++) {
                const float4 hv = h4[i4];
                const ull h01 = pk(hv.x, hv.y), h23 = pk(hv.z, hv.w);
                fma2(ar, wr2[2 * i4], h01); fma2(az, wz2[2 * i4], h01); fma2(an, wn2[2 * i4], h01);
                fma2(ar, wr2[2 * i4 + 1], h23); fma2(az, wz2[2 * i4 + 1], h23); fma2(an, wn2[2 * i4 + 1], h23);
            }
            const float2 fr = upk(ar), fz = upk(az), fn = upk(an);
            const float r = sigmoidf_(gxr + fr.x + fr.y);
            const float z = sigmoidf_(gxz + fz.x + fz.y);
            const float n = tanhf_(gxn + r * (fn.x + fn.y));
            const float hn = fmaf(z, h - n, n);
            HSb[(curl ^ 1) * 64 + j] = hn;
            h = hn;
            gbar(barid);
            curl ^= 1;
        }
    }

    // ---- head (h is in HS buffer 0) ----
    float o = head_b[j];
#pragma unroll 8
    for (int i = 0; i < 64; i++) o = fmaf(head_w[j * 64 + i], HSb[i], o);
    out[(size_t)bg * VV + j] = o;
}

extern "C" void kernel_launch(void* const* d_in, const int* in_sizes, int n_in,
                              void* d_out, int out_size) {
    const int*   seq      = (const int*)  d_in[0];
    const float* memory   = (const float*)d_in[1];
    const float* embed_w  = (const float*)d_in[2];
    const float* w_ih     = (const float*)d_in[3];
    const float* w_hh     = (const float*)d_in[4];
    const float* b_ih     = (const float*)d_in[5];
    const float* b_hh     = (const float*)d_in[6];
    const float* key_w    = (const float*)d_in[7];
    const float* key_b    = (const float*)d_in[8];   // cancels in softmax (constant over m)
    const float* val_w    = (const float*)d_in[9];
    const float* val_b    = (const float*)d_in[10];
    const float* query_w  = (const float*)d_in[11];
    const float* query_b  = (const float*)d_in[12];
    const float* head_w   = (const float*)d_in[13];
    const float* head_b   = (const float*)d_in[14];
    (void)key_b;

    setup_k<<<113, 256>>>(embed_w, w_ih, b_ih, key_w, val_w, val_b, query_w, query_b);

    const size_t shmem = (size_t)SMEM_FLOATS * sizeof(float);
    cudaFuncSetAttribute(ffm_kernel, cudaFuncAttributeMaxDynamicSharedMemorySize, (int)shmem);
    ffm_kernel<<<NGRID, NT, shmem>>>(seq, memory, w_hh, b_hh, head_w, head_b, (float*)d_out);
}

// round 11
// speedup vs baseline: 1.0791x; 1.0791x over previous
#include <cuda_runtime.h>
#include <cstdint>

#define RFQ 16
#define NCHUNK 128
#define NB 4
#define NT 512
#define NGRID 128
#define TS 68
#define TILE_F 4368   // floats per tile buffer (64*68 + skew headroom)

typedef unsigned long long ull;

// ---- precomputed tables (setup kernel) ----
__device__ float VPg[12288];      // [3][64 vocab][64 j]  (b_ih + b_hh(r,z) folded)
__device__ float RVTg[64 * 193];  // [64 i][192 row], stride 193 (bank skew)
__device__ float ATg[64 * 65];    // [64 c][64 i], stride 65
__device__ float A0g[64];
__device__ float RV0g[192];

// smem offsets (floats)
#define OFF_RVT   0              // 12352
#define OFF_AT    12352          // 4160
#define OFF_A0    16512          // 64
#define OFF_RV0   16576          // 192
#define OFF_TILE  16768          // 8 * 4368 = 34944 (4 groups x 2 bufs)
#define OFF_HS    51712          // 4 * 128
#define OFF_QS    52224          // 4 * 64
#define OFF_SS    52480
#define OFF_ES    52736
#define OFF_RS    52992
#define OFF_TOK   53248          // 4 * 16 ints
#define SMEM_FLOATS 53312        // 213248 bytes

#define TROW(m) ((m) * TS + (((m) & 32) >> 1))   // +16 skew for rows 32..63

__device__ __forceinline__ void gbar(int id) {
    asm volatile("bar.sync %0, 128;" :: "r"(id) : "memory");
}
__device__ __forceinline__ float sigmoidf_(float x) {
    float e = __expf(-x);
    return __fdividef(1.f, 1.f + e);
}
__device__ __forceinline__ float tanhf_(float x) {
    float e = __expf(2.f * x);
    return 1.f - __fdividef(2.f, e + 1.f);
}
__device__ __forceinline__ ull pk(float a, float b) {
    ull r; asm("mov.b64 %0, {%1,%2};" : "=l"(r) : "f"(a), "f"(b)); return r;
}
__device__ __forceinline__ void fma2(ull& d, ull a, ull b) {
    asm("fma.rn.f32x2 %0, %1, %2, %0;" : "+l"(d) : "l"(a), "l"(b));
}
__device__ __forceinline__ float2 upk(ull a) {
    float2 f; asm("mov.b64 {%0,%1}, %2;" : "=f"(f.x), "=f"(f.y) : "l"(a)); return f;
}
__device__ __forceinline__ uint32_t s2u(const void* p) {
    return (uint32_t)__cvta_generic_to_shared(p);
}
__device__ __forceinline__ void cp16(uint32_t d, const float4* s) {
    asm volatile("cp.async.cg.shared.global [%0], [%1], 16;" :: "r"(d), "l"(s));
}
__device__ __forceinline__ void cpcommit() { asm volatile("cp.async.commit_group;"); }
template <int N> __device__ __forceinline__ void cpwait() {
    asm volatile("cp.async.wait_group %0;" :: "n"(N) : "memory");
}

// issue one 64x64 tile copy (8 x cp.async.16 per thread, 128 threads/group)
__device__ __forceinline__ void issue_tile(uint32_t tb_bytes, const float4* mt4, int tid_b) {
#pragma unroll
    for (int it = 0; it < 8; it++) {
        const int e4 = it * 128 + tid_b;
        const int r = e4 >> 4, c4 = e4 & 15;
        cp16(tb_bytes + (uint32_t)((TROW(r) + c4 * 4) * 4), mt4 + e4);
    }
    cpcommit();
}

// ---- setup kernel: fold all token/attention algebra once ----
__global__ void setup_k(const float* __restrict__ embed_w, const float* __restrict__ w_ih,
                        const float* __restrict__ b_ih, const float* __restrict__ b_hh,
                        const float* __restrict__ key_w, const float* __restrict__ val_w,
                        const float* __restrict__ val_b, const float* __restrict__ query_w,
                        const float* __restrict__ query_b)
{
    const int idx = blockIdx.x * 256 + threadIdx.x;
    if (idx < 12288) {
        // VP[g][v][jj] = emb[v].W_ih_x[row] + b_ih[row] + (g<2 ? b_hh[row] : 0)
        const int g = idx >> 12, v = (idx >> 6) & 63, jj = idx & 63;
        const int row = g * 64 + jj;
        float acc = b_ih[row] + (g < 2 ? b_hh[row] : 0.f);
#pragma unroll 8
        for (int c = 0; c < 64; c++) acc = fmaf(embed_w[v * 64 + c], w_ih[row * 128 + c], acc);
        VPg[idx] = acc;
    } else if (idx < 24576) {
        // RVT[i][row] = sum_k W_ih_ret[row][k] * val_w[k][i]   (stride-193)
        const int t = idx - 12288;
        const int i = t / 192, row = t % 192;
        float acc = 0.f;
#pragma unroll 8
        for (int k = 0; k < 64; k++) acc = fmaf(w_ih[row * 128 + 64 + k], val_w[k * 64 + i], acc);
        RVTg[i * 193 + row] = acc;
    } else if (idx < 28672) {
        // AT[c][i] = scale * sum_k key_w[k][i]*query_w[k][c]   (stride-65)
        const int t = idx - 24576;
        const int c = t >> 6, i = t & 63;
        float acc = 0.f;
#pragma unroll 8
        for (int k = 0; k < 64; k++) acc = fmaf(key_w[k * 64 + i], query_w[k * 64 + c], acc);
        ATg[c * 65 + i] = acc * 0.125f;
    } else if (idx < 28736) {
        const int i = idx - 28672;
        float acc = 0.f;
#pragma unroll 8
        for (int k = 0; k < 64; k++) acc = fmaf(key_w[k * 64 + i], query_b[k], acc);
        A0g[i] = acc * 0.125f;
    } else if (idx < 28928) {
        const int row = idx - 28736;
        float acc = 0.f;
#pragma unroll 8
        for (int k = 0; k < 64; k++) acc = fmaf(w_ih[row * 128 + 64 + k], val_b[k], acc);
        RV0g[row] = acc;
    }
}

__global__ void __launch_bounds__(NT, 1) ffm_kernel(
    const int*   __restrict__ seq,
    const float* __restrict__ memory,
    const float* __restrict__ w_hh,
    const float* __restrict__ b_hh,
    const float* __restrict__ head_w,
    const float* __restrict__ head_b,
    float* __restrict__ out)
{
    extern __shared__ float sm[];
    float* RVT = sm + OFF_RVT;
    float* AT  = sm + OFF_AT;
    float* A0  = sm + OFF_A0;
    float* RV0 = sm + OFF_RV0;

    const int tid   = threadIdx.x;
    const int tid_b = tid & 127;          // within batch group
    const int j     = tid_b >> 1;         // gate row 0..63
    const int p     = tid_b & 1;          // i-half: [32p, 32p+32)
    const int bl    = tid >> 7;           // batch group 0..3
    const int bg    = blockIdx.x * NB + bl;
    const int barid = bl + 1;

    // ---- copy tables into shared ----
    for (int e = tid; e < 12352; e += NT) RVT[e] = RVTg[e];
    for (int e = tid; e < 4160;  e += NT) AT[e]  = ATg[e];
    if (tid < 64)  A0[tid]  = A0g[tid];
    if (tid < 192) RV0[tid] = RV0g[tid];

    float* TILE0 = sm + OFF_TILE + (bl * 2 + 0) * TILE_F;
    float* TILE1 = sm + OFF_TILE + (bl * 2 + 1) * TILE_F;
    const uint32_t u0 = s2u(TILE0), u1 = s2u(TILE1);
    float* HSb = sm + OFF_HS + bl * 128;
    float* QSb = sm + OFF_QS + bl * 64;
    float* SSb = sm + OFF_SS + bl * 64;
    float* ESb = sm + OFF_ES + bl * 64;
    float* RSb = sm + OFF_RS + bl * 64;
    int*   TOKb = (int*)(sm + OFF_TOK) + bl * 16;

    if (!p) HSb[j] = 0.f;

    // ---- load W_hh half-rows into registers (once, forever) ----
    ull wr2[16], wz2[16], wn2[16];
    {
        const float4* wh4 = (const float4*)w_hh;
        const int base = (j * 64 + 32 * p) >> 2;
#pragma unroll
        for (int k = 0; k < 8; k++) {
            float4 a = wh4[base + k];
            float4 b = wh4[base + 1024 + k];    // (64+j)*64/4 = base + 1024
            float4 c = wh4[base + 2048 + k];
            wr2[2 * k] = pk(a.x, a.y); wr2[2 * k + 1] = pk(a.z, a.w);
            wz2[2 * k] = pk(b.x, b.y); wz2[2 * k + 1] = pk(b.z, b.w);
            wn2[2 * k] = pk(c.x, c.y); wn2[2 * k + 1] = pk(c.z, c.w);
        }
    }
    const float bhn = b_hh[128 + j];

    float h = 0.f;
    const float4* mt4 = (const float4*)(memory + (size_t)bg * (256 * 64));
    const int* seqb = seq + (size_t)bg * 2048;
    __syncthreads();

    // prefetch tiles 0,1 of chunk 0
    issue_tile(u0, mt4, tid_b);
    issue_tile(u1, mt4 + 1024, tid_b);

#pragma unroll 1
    for (int ch = 0; ch < NCHUNK; ch++) {
        if (tid_b < 16) TOKb[tid_b] = seqb[ch * RFQ + tid_b];
        // query: qt[j] partial over c-half, shfl-combined
        {
            float qt = 0.f;
#pragma unroll
            for (int ci = 0; ci < 32; ci++) {
                const int c = 32 * p + ((ci + 16 * p) & 31);
                qt = fmaf(AT[c * 65 + j], HSb[c], qt);
            }
            qt += __shfl_xor_sync(~0u, qt, 1);
            if (!p) QSb[j] = qt + A0[j];
        }

        // ---- attention: 4 tiles, online softmax, double-buffered cp.async ----
        float Mx = -1e30f, D = 0.f, macc = 0.f;
#pragma unroll
        for (int t = 0; t < 4; t++) {
            if (t < 3) cpwait<1>(); else cpwait<0>();
            gbar(barid);
            const float* tb = (t & 1) ? TILE1 : TILE0;
            // score row j (fma2, p-rotated columns -> conflict-free)
            float s;
            {
                ull s2 = 0ull;
                const float* rowp = tb + TROW(j);
#pragma unroll
                for (int k = 0; k < 8; k++) {
                    const int kk = (k + 4 * p) & 7;
                    const int col = 32 * p + 4 * kk;
                    const float4 qv = *(const float4*)(QSb + col);
                    const float4 rv = *(const float4*)(rowp + col);
                    fma2(s2, pk(qv.x, qv.y), pk(rv.x, rv.y));
                    fma2(s2, pk(qv.z, qv.w), pk(rv.z, rv.w));
                }
                const float2 sf = upk(s2);
                s = sf.x + sf.y;
            }
            s += __shfl_xor_sync(~0u, s, 1);
            if (!p) SSb[j] = s;
            gbar(barid);
            // max over half + partner
            float tm = -1e30f;
#pragma unroll 8
            for (int mi = 0; mi < 32; mi++) tm = fmaxf(tm, SSb[32 * p + mi]);
            tm = fmaxf(tm, __shfl_xor_sync(~0u, tm, 1));
            const float nM = fmaxf(Mx, tm);
            const float alpha = __expf(Mx - nM);
            const float em = __expf(s - nM);
            if (!p) ESb[j] = em;
            gbar(barid);
            macc *= alpha; D *= alpha;
            const float* colp = tb + (p ? TROW(32) : 0) + j;
#pragma unroll 8
            for (int mi = 0; mi < 32; mi++) {
                const float e = ESb[32 * p + mi];
                macc = fmaf(e, colp[mi * TS], macc);
                D += e;
            }
            Mx = nM;
            gbar(barid);
            // refill the buffer just consumed with tile t+2
            if (t < 2) {
                issue_tile((t & 1) ? u1 : u0, mt4 + (t + 2) * 1024, tid_b);
            }
        }
        {
            const float mtt = macc + __shfl_xor_sync(~0u, macc, 1);
            const float Dt  = D + __shfl_xor_sync(~0u, D, 1);
            if (!p) RSb[j] = mtt / Dt;
        }
        gbar(barid);

        // prefetch next chunk's tiles 0,1 (memory is chunk-invariant; overlaps GRU)
        if (ch != NCHUNK - 1) {
            issue_tile(u0, mt4, tid_b);
            issue_tile(u1, mt4 + 1024, tid_b);
        }

        // r_proj partials over i-half, shfl-combined (both lanes keep totals)
        float rp_r = 0.f, rp_z = 0.f, rp_n = 0.f;
#pragma unroll
        for (int ii = 0; ii < 32; ii++) {
            const int i = 32 * p + ((ii + 16 * p) & 31);
            const float rv = RSb[i];
            const float* rt = RVT + i * 193;
            rp_r = fmaf(rt[j], rv, rp_r);
            rp_z = fmaf(rt[64 + j], rv, rp_z);
            rp_n = fmaf(rt[128 + j], rv, rp_n);
        }
        rp_r += __shfl_xor_sync(~0u, rp_r, 1);
        rp_z += __shfl_xor_sync(~0u, rp_z, 1);
        rp_n += __shfl_xor_sync(~0u, rp_n, 1);
        rp_r += RV0[j]; rp_z += RV0[64 + j]; rp_n += RV0[128 + j];

        // ---- 16 GRU steps: split-K fma2 dots + shfl combine ----
        int curl = 0;
#pragma unroll 1
        for (int st = 0; st < RFQ; st++) {
            const int tok = TOKb[st];
            const float* vp = VPg + tok * 64 + j;
            const float gxr = vp[0] + rp_r;
            const float gxz = vp[4096] + rp_z;
            const float gxn = vp[8192] + rp_n;
            const float4* h4 = (const float4*)(HSb + curl * 64 + 32 * p);
            ull ar = 0ull, az = 0ull, an = 0ull;
#pragma unroll
            for (int k = 0; k < 8; k++) {
                const float4 hv = h4[k];
                const ull h01 = pk(hv.x, hv.y), h23 = pk(hv.z, hv.w);
                fma2(ar, wr2[2 * k], h01); fma2(az, wz2[2 * k], h01); fma2(an, wn2[2 * k], h01);
                fma2(ar, wr2[2 * k + 1], h23); fma2(az, wz2[2 * k + 1], h23); fma2(an, wn2[2 * k + 1], h23);
            }
            float2 f;
            f = upk(ar); float ars = f.x + f.y; ars += __shfl_xor_sync(~0u, ars, 1);
            f = upk(az); float azs = f.x + f.y; azs += __shfl_xor_sync(~0u, azs, 1);
            f = upk(an); float ans = f.x + f.y; ans += __shfl_xor_sync(~0u, ans, 1);
            const float r = sigmoidf_(gxr + ars);
            const float z = sigmoidf_(gxz + azs);
            const float n = tanhf_(gxn + r * (ans + bhn));
            const float hn = fmaf(z, h - n, n);
            if (!p) HSb[(curl ^ 1) * 64 + j] = hn;
            h = hn;
            gbar(barid);
            curl ^= 1;
        }
    }

    // ---- head (h ends in HS buffer 0) ----
    {
        float o = 0.f;
        const float4* hw4 = (const float4*)(head_w + j * 64 + 32 * p);
        const float4* hf4 = (const float4*)(HSb + 32 * p);
#pragma unroll
        for (int k = 0; k < 8; k++) {
            const float4 w = hw4[k], v = hf4[k];
            o = fmaf(w.x, v.x, o); o = fmaf(w.y, v.y, o);
            o = fmaf(w.z, v.z, o); o = fmaf(w.w, v.w, o);
        }
        o += __shfl_xor_sync(~0u, o, 1);
        if (!p) out[(size_t)bg * 64 + j] = o + head_b[j];
    }
}

extern "C" void kernel_launch(void* const* d_in, const int* in_sizes, int n_in,
                              void* d_out, int out_size) {
    const int*   seq      = (const int*)  d_in[0];
    const float* memory   = (const float*)d_in[1];
    const float* embed_w  = (const float*)d_in[2];
    const float* w_ih     = (const float*)d_in[3];
    const float* w_hh     = (const float*)d_in[4];
    const float* b_ih     = (const float*)d_in[5];
    const float* b_hh     = (const float*)d_in[6];
    const float* key_w    = (const float*)d_in[7];
    const float* key_b    = (const float*)d_in[8];   // cancels in softmax
    const float* val_w    = (const float*)d_in[9];
    const float* val_b    = (const float*)d_in[10];
    const float* query_w  = (const float*)d_in[11];
    const float* query_b  = (const float*)d_in[12];
    const float* head_w   = (const float*)d_in[13];
    const float* head_b   = (const float*)d_in[14];
    (void)key_b;

    setup_k<<<113, 256>>>(embed_w, w_ih, b_ih, b_hh, key_w, val_w, val_b, query_w, query_b);

    const size_t shmem = (size_t)SMEM_FLOATS * sizeof(float);
    cudaFuncSetAttribute(ffm_kernel, cudaFuncAttributeMaxDynamicSharedMemorySize, (int)shmem);
    ffm_kernel<<<NGRID, NT, shmem>>>(seq, memory, w_hh, b_hh, head_w, head_b, (float*)d_out);
}